// round 1
// baseline (speedup 1.0000x reference)
#include <cuda_runtime.h>
#include <cuda_bf16.h>
#include <math.h>
#include <stdint.h>

#define NTOT  8192
#define BHALF 4096
#define DDIM  256
#define MT    64      // rows per block
#define CT    128     // cols per column tile
#define AS    264     // padded smem stride in bf16 elems (264*2=528B, 16B aligned, +4 banks/row)

// Scratch (no cudaMalloc allowed): normalized bf16 vectors + scalar accumulator
__device__ __nv_bfloat16 g_zhat[NTOT * DDIM];
__device__ float g_accum;

// ---------------------------------------------------------------------------
// fast exp2-based exp(sim): e^(cos/T) = 2^(cos * log2e/T), |arg| <= ~2.95
// ---------------------------------------------------------------------------
__device__ __forceinline__ float fexp2(float y) {
    float r = floorf(y);
    float f = y - r;                      // [0,1)
    float x = f * 0.6931471805599453f;    // f*ln2, [0, ln2)
    // e^x Taylor deg-6 (max rel err ~3e-5 at x=ln2; averages out over 8191 terms)
    float p = 1.3888889e-3f;              // 1/720
    p = fmaf(p, x, 8.3333333e-3f);        // 1/120
    p = fmaf(p, x, 4.1666667e-2f);        // 1/24
    p = fmaf(p, x, 0.16666667f);          // 1/6
    p = fmaf(p, x, 0.5f);
    p = fmaf(p, x, 1.0f);
    p = fmaf(p, x, 1.0f);
    return p * __int_as_float(((int)r + 127) << 23);   // * 2^r, r in [-3,3]
}

// ---------------------------------------------------------------------------
__global__ void k_init() { g_accum = 0.0f; }

// One warp per row: norm + normalize + bf16 store
__global__ void k_prep(const float* __restrict__ zi, const float* __restrict__ zj) {
    int row  = blockIdx.x * 8 + (threadIdx.x >> 5);
    int lane = threadIdx.x & 31;
    const float* src = (row < BHALF) ? (zi + (size_t)row * DDIM)
                                     : (zj + (size_t)(row - BHALF) * DDIM);
    float4 v0 = ((const float4*)src)[lane * 2 + 0];
    float4 v1 = ((const float4*)src)[lane * 2 + 1];
    float ss = v0.x*v0.x + v0.y*v0.y + v0.z*v0.z + v0.w*v0.w
             + v1.x*v1.x + v1.y*v1.y + v1.z*v1.z + v1.w*v1.w;
    #pragma unroll
    for (int o = 16; o; o >>= 1) ss += __shfl_xor_sync(0xffffffffu, ss, o);
    float rinv = rsqrtf(ss);   // norms ~16 for N(0,1) D=256: eps branch never binds

    __nv_bfloat162 h0 = __floats2bfloat162_rn(v0.x * rinv, v0.y * rinv);
    __nv_bfloat162 h1 = __floats2bfloat162_rn(v0.z * rinv, v0.w * rinv);
    __nv_bfloat162 h2 = __floats2bfloat162_rn(v1.x * rinv, v1.y * rinv);
    __nv_bfloat162 h3 = __floats2bfloat162_rn(v1.z * rinv, v1.w * rinv);
    uint4 pack;
    pack.x = *(uint32_t*)&h0;  pack.y = *(uint32_t*)&h1;
    pack.z = *(uint32_t*)&h2;  pack.w = *(uint32_t*)&h3;
    *(uint4*)(g_zhat + (size_t)row * DDIM + lane * 8) = pack;
}

// ---------------------------------------------------------------------------
// Main: each block owns MT=64 rows, sweeps all 8192 columns in CT=128 tiles.
// 8 warps = 4 M-subtiles (16 rows) x 2 N-halves (64 cols).
// mma.sync m16n8k16 bf16, fp32 accumulate. Online sum-exp (no max needed:
// |sim| <= 1/T ~ 2, exp in [0.05, 7.4], row-sum < 61K -> fp32 safe).
// ---------------------------------------------------------------------------
__global__ void __launch_bounds__(256) k_main() {
    extern __shared__ __nv_bfloat16 sm[];
    __nv_bfloat16* Ash = sm;              // MT x AS
    __nv_bfloat16* Bsh = sm + MT * AS;    // CT x AS
    __shared__ float S_sh[MT];
    __shared__ float pos_sh[MT];
    __shared__ float blk_sum;

    const int tid  = threadIdx.x;
    const int lane = tid & 31;
    const int warp = tid >> 5;
    const int wm   = warp & 3;            // M subtile 0..3
    const int wn   = warp >> 2;           // N half 0..1
    const int l4   = lane >> 2;
    const int lm   = lane & 3;
    const int row_base = blockIdx.x * MT;

    if (tid < MT) { S_sh[tid] = 0.0f; pos_sh[tid] = 0.0f; }
    if (tid == 0) blk_sum = 0.0f;

    // Load A tile once (64 x 256 bf16), 16B chunks
    #pragma unroll
    for (int i = 0; i < 8; i++) {
        int c = tid + i * 256;
        int r = c >> 5;
        int off = (c & 31) * 8;
        *(uint4*)(Ash + r * AS + off) =
            *(const uint4*)(g_zhat + (size_t)(row_base + r) * DDIM + off);
    }

    const int arow0 = wm * 16 + l4;
    const int gr0 = row_base + arow0;
    const int gr1 = gr0 + 8;
    const int diag_ct = row_base >> 7;
    const int pos_ct  = ((row_base + BHALF) & (NTOT - 1)) >> 7;
    const float CEXP = 2.8853900817779268f;   // log2(e)/T, T=0.5

    float rs0 = 0.0f, rs1 = 0.0f;

    for (int ct = 0; ct < NTOT / CT; ct++) {
        const int col_base = ct * CT;
        __syncthreads();   // previous tile's B reads done (also covers A-load on ct=0)
        #pragma unroll
        for (int i = 0; i < 16; i++) {
            int c = tid + i * 256;
            int r = c >> 5;
            int off = (c & 31) * 8;
            *(uint4*)(Bsh + r * AS + off) =
                *(const uint4*)(g_zhat + (size_t)(col_base + r) * DDIM + off);
        }
        __syncthreads();

        float acc[8][4];
        #pragma unroll
        for (int t = 0; t < 8; t++)
            #pragma unroll
            for (int c = 0; c < 4; c++) acc[t][c] = 0.0f;

        #pragma unroll
        for (int ks = 0; ks < 16; ks++) {
            const int k0 = ks * 16;
            uint32_t a0 = *(uint32_t*)(Ash + (arow0    ) * AS + k0     + lm * 2);
            uint32_t a1 = *(uint32_t*)(Ash + (arow0 + 8) * AS + k0     + lm * 2);
            uint32_t a2 = *(uint32_t*)(Ash + (arow0    ) * AS + k0 + 8 + lm * 2);
            uint32_t a3 = *(uint32_t*)(Ash + (arow0 + 8) * AS + k0 + 8 + lm * 2);
            #pragma unroll
            for (int t = 0; t < 8; t++) {
                const int bn = wn * 64 + t * 8 + l4;
                uint32_t b0 = *(uint32_t*)(Bsh + bn * AS + k0     + lm * 2);
                uint32_t b1 = *(uint32_t*)(Bsh + bn * AS + k0 + 8 + lm * 2);
                asm volatile(
                    "mma.sync.aligned.m16n8k16.row.col.f32.bf16.bf16.f32 "
                    "{%0,%1,%2,%3}, {%4,%5,%6,%7}, {%8,%9}, {%0,%1,%2,%3};"
                    : "+f"(acc[t][0]), "+f"(acc[t][1]), "+f"(acc[t][2]), "+f"(acc[t][3])
                    : "r"(a0), "r"(a1), "r"(a2), "r"(a3), "r"(b0), "r"(b1));
            }
        }

        // Epilogue: exp(sim) accumulation; diagonal/positive only in 2 known tiles
        const bool special = (ct == diag_ct) || (ct == pos_ct);
        #pragma unroll
        for (int t = 0; t < 8; t++) {
            const int gc0 = col_base + wn * 64 + t * 8 + lm * 2;
            #pragma unroll
            for (int c = 0; c < 4; c++) {
                float s = acc[t][c];                 // cosine
                float e = fexp2(s * CEXP);           // exp(cos/T)
                if (special) {
                    int gc = gc0 + (c & 1);
                    int gr = (c < 2) ? gr0 : gr1;
                    if (gc == gr) e = 0.0f;          // mask self-similarity
                    if (gc == ((gr + BHALF) & (NTOT - 1)))
                        pos_sh[gr - row_base] = s * 2.0f;   // sim = cos/T
                }
                if (c < 2) rs0 += e; else rs1 += e;
            }
        }
    }

    // Reduce row-sums: 4 lanes per row within quad, then 2 N-half warps via smem
    rs0 += __shfl_xor_sync(0xffffffffu, rs0, 1);
    rs0 += __shfl_xor_sync(0xffffffffu, rs0, 2);
    rs1 += __shfl_xor_sync(0xffffffffu, rs1, 1);
    rs1 += __shfl_xor_sync(0xffffffffu, rs1, 2);
    if (lm == 0) {
        atomicAdd(&S_sh[arow0    ], rs0);
        atomicAdd(&S_sh[arow0 + 8], rs1);
    }
    __syncthreads();

    if (tid < MT) {
        float v = logf(S_sh[tid]) - pos_sh[tid];   // lse - pos for this row
        atomicAdd(&blk_sum, v);
    }
    __syncthreads();
    if (tid == 0) atomicAdd(&g_accum, blk_sum);
}

__global__ void k_final(float* out) { out[0] = g_accum * (1.0f / NTOT); }

// ---------------------------------------------------------------------------
extern "C" void kernel_launch(void* const* d_in, const int* in_sizes, int n_in,
                              void* d_out, int out_size) {
    const float* zi = (const float*)d_in[0];
    const float* zj = (const float*)d_in[1];
    float* out = (float*)d_out;

    size_t smem = (size_t)(MT + CT) * AS * sizeof(__nv_bfloat16);  // 101,376 B
    cudaFuncSetAttribute(k_main, cudaFuncAttributeMaxDynamicSharedMemorySize, (int)smem);

    k_init<<<1, 1>>>();
    k_prep<<<NTOT / 8, 256>>>(zi, zj);
    k_main<<<NTOT / MT, 256, smem>>>();
    k_final<<<1, 1>>>(out);
}

// round 3
// speedup vs baseline: 1.9473x; 1.9473x over previous
#include <cuda_runtime.h>
#include <cuda_bf16.h>
#include <math.h>
#include <stdint.h>

#define NTOT   8192
#define BHALF  4096
#define DDIM   256
#define MT     128                  // rows per block
#define CT     128                  // cols per tile
#define NTILES (BHALF / CT)         // 32 tiles per column-half
#define ASB    528                  // smem row stride in BYTES (264 bf16; 33*16B -> conflict-free)
#define TILE_B (MT * ASB)           // 67584 bytes per tile buffer

// Scratch: normalized bf16 vectors, per-row sum-exp, per-row positive logit
__device__ __nv_bfloat16 g_zhat[NTOT * DDIM];
__device__ float g_rowsum[NTOT];
__device__ float g_pos[NTOT];

// ---------------------------------------------------------------------------
__device__ __forceinline__ uint32_t smem_u32(const void* p) {
    uint32_t a;
    asm("{ .reg .u64 t; cvta.to.shared.u64 t, %1; cvt.u32.u64 %0, t; }"
        : "=r"(a) : "l"(p));
    return a;
}
__device__ __forceinline__ float ex2f(float x) {     // 2^x on MUFU pipe
    float r;
    asm("ex2.approx.f32 %0, %1;" : "=f"(r) : "f"(x));
    return r;
}
#define CP_ASYNC16(dst, src) \
    asm volatile("cp.async.cg.shared.global [%0], [%1], 16;" :: "r"(dst), "l"(src))
#define CP_COMMIT() asm volatile("cp.async.commit_group;" ::: "memory")
#define CP_WAIT(n)  asm volatile("cp.async.wait_group %0;" :: "n"(n) : "memory")

#define LDSM_X4(r0, r1, r2, r3, a)                                        \
    asm volatile("ldmatrix.sync.aligned.m8n8.x4.shared.b16 {%0,%1,%2,%3}, [%4];" \
        : "=r"(r0), "=r"(r1), "=r"(r2), "=r"(r3) : "r"(a))

#define MMA16816(d, a, b0, b1)                                            \
    asm volatile("mma.sync.aligned.m16n8k16.row.col.f32.bf16.bf16.f32 "   \
        "{%0,%1,%2,%3}, {%4,%5,%6,%7}, {%8,%9}, {%0,%1,%2,%3};"           \
        : "+f"((d)[0]), "+f"((d)[1]), "+f"((d)[2]), "+f"((d)[3])          \
        : "r"((a)[0]), "r"((a)[1]), "r"((a)[2]), "r"((a)[3]), "r"(b0), "r"(b1))

// ---------------------------------------------------------------------------
__global__ void k_init() {
    g_rowsum[blockIdx.x * 1024 + threadIdx.x] = 0.0f;
}

// One warp per row: norm + normalize + bf16 store
__global__ void k_prep(const float* __restrict__ zi, const float* __restrict__ zj) {
    int row  = blockIdx.x * 8 + (threadIdx.x >> 5);
    int lane = threadIdx.x & 31;
    const float* src = (row < BHALF) ? (zi + (size_t)row * DDIM)
                                     : (zj + (size_t)(row - BHALF) * DDIM);
    float4 v0 = ((const float4*)src)[lane * 2 + 0];
    float4 v1 = ((const float4*)src)[lane * 2 + 1];
    float ss = v0.x*v0.x + v0.y*v0.y + v0.z*v0.z + v0.w*v0.w
             + v1.x*v1.x + v1.y*v1.y + v1.z*v1.z + v1.w*v1.w;
    #pragma unroll
    for (int o = 16; o; o >>= 1) ss += __shfl_xor_sync(0xffffffffu, ss, o);
    float rinv = rsqrtf(ss);   // norms ~16 for N(0,1) D=256: eps never binds

    __nv_bfloat162 h0 = __floats2bfloat162_rn(v0.x * rinv, v0.y * rinv);
    __nv_bfloat162 h1 = __floats2bfloat162_rn(v0.z * rinv, v0.w * rinv);
    __nv_bfloat162 h2 = __floats2bfloat162_rn(v1.x * rinv, v1.y * rinv);
    __nv_bfloat162 h3 = __floats2bfloat162_rn(v1.z * rinv, v1.w * rinv);
    uint4 pack;
    pack.x = *(uint32_t*)&h0;  pack.y = *(uint32_t*)&h1;
    pack.z = *(uint32_t*)&h2;  pack.w = *(uint32_t*)&h3;
    *(uint4*)(g_zhat + (size_t)row * DDIM + lane * 8) = pack;
}

// ---------------------------------------------------------------------------
// Async tile loader: 128 rows x 256 bf16 (512B payload per 528B smem row).
// 256 threads x 16 chunks of 16B.
// ---------------------------------------------------------------------------
__device__ __forceinline__ void load_tile_async(uint32_t dst, int grow0) {
    const int tid = threadIdx.x;
    #pragma unroll
    for (int i = 0; i < 16; i++) {
        int c   = tid + i * 256;
        int r   = c >> 5;
        int off = (c & 31) * 16;
        CP_ASYNC16(dst + r * ASB + off,
                   (const char*)g_zhat + (size_t)(grow0 + r) * 512 + off);
    }
}

// ---------------------------------------------------------------------------
// Main: block = 128 rows x one 4096-col half. 8 warps = 4 M-tiles(32) x 2
// N-halves(64). mma.sync m16n8k16 bf16, ldmatrix fragments, cp.async double
// buffer, MUFU exp epilogue on register-resident accumulators.
// ---------------------------------------------------------------------------
__global__ void __launch_bounds__(256) k_main() {
    extern __shared__ char sm[];
    const uint32_t sA  = smem_u32(sm);
    const uint32_t sB0 = sA + TILE_B;

    const int tid  = threadIdx.x;
    const int lane = tid & 31;
    const int warp = tid >> 5;
    const int wm   = warp & 3;             // M subtile (32 rows)
    const int wn   = warp >> 2;            // N half (64 cols)
    const int l4   = lane >> 2;
    const int lm   = lane & 3;
    const int row_base = (blockIdx.x >> 1) * MT;
    const int col0     = (blockIdx.x & 1) * BHALF;

    // ldmatrix per-lane base offsets (bytes), k-step adds ks*32
    // A (m16k16, x4): groups [m0-7@k0, m8-15@k0, m0-7@k8, m8-15@k8]
    uint32_t aoff[2];
    #pragma unroll
    for (int m = 0; m < 2; m++) {
        int arow = wm * 32 + m * 16 + (lane & 15);
        aoff[m] = sA + (uint32_t)arow * ASB + (uint32_t)(lane >> 4) * 16;
    }
    // B (n16k16, x4): groups [n0-7@k0, n0-7@k8, n8-15@k0, n8-15@k8]
    uint32_t boff[4];
    #pragma unroll
    for (int nt = 0; nt < 4; nt++) {
        int brow = wn * 64 + nt * 16 + (lane & 7) + ((lane >> 4) << 3);
        boff[nt] = (uint32_t)brow * ASB + (uint32_t)((lane >> 3) & 1) * 16;
    }

    // Kick off A + B0 as one cp.async group
    load_tile_async(sA, row_base);
    load_tile_async(sB0, col0);
    CP_COMMIT();

    const int pos_tile_col = (row_base + BHALF) & (NTOT - 1);
    const float CEXP = 2.8853900817779268f;      // log2(e)/T, T = 0.5
    float rs[2][2] = {{0.f, 0.f}, {0.f, 0.f}};   // [m][c-half] row partial sums

    for (int ct = 0; ct < NTILES; ct++) {
        const uint32_t bufc = sB0 + (uint32_t)(ct & 1) * TILE_B;
        __syncthreads();                          // prev reads of buf[(ct+1)&1] done
        if (ct + 1 < NTILES) {
            load_tile_async(sB0 + (uint32_t)((ct + 1) & 1) * TILE_B,
                            col0 + (ct + 1) * CT);
            CP_COMMIT();
            CP_WAIT(1);                           // tile ct resident
        } else {
            CP_WAIT(0);
        }
        __syncthreads();

        float acc[2][8][4];
        #pragma unroll
        for (int m = 0; m < 2; m++)
            #pragma unroll
            for (int n = 0; n < 8; n++)
                #pragma unroll
                for (int c = 0; c < 4; c++) acc[m][n][c] = 0.0f;

        #pragma unroll
        for (int ks = 0; ks < 16; ks++) {
            const uint32_t kb = (uint32_t)ks * 32;
            uint32_t a[2][4], b[4][4];
            #pragma unroll
            for (int m = 0; m < 2; m++)
                LDSM_X4(a[m][0], a[m][1], a[m][2], a[m][3], aoff[m] + kb);
            #pragma unroll
            for (int nt = 0; nt < 4; nt++)
                LDSM_X4(b[nt][0], b[nt][1], b[nt][2], b[nt][3], bufc + boff[nt] + kb);
            #pragma unroll
            for (int m = 0; m < 2; m++)
                #pragma unroll
                for (int nt = 0; nt < 4; nt++) {
                    MMA16816(acc[m][nt * 2 + 0], a[m], b[nt][0], b[nt][1]);
                    MMA16816(acc[m][nt * 2 + 1], a[m], b[nt][2], b[nt][3]);
                }
        }

        // Epilogue on register accumulators
        const int tile_col = col0 + ct * CT;
        const bool special = (tile_col == row_base) || (tile_col == pos_tile_col);
        if (!special) {
            #pragma unroll
            for (int m = 0; m < 2; m++)
                #pragma unroll
                for (int n = 0; n < 8; n++)
                    #pragma unroll
                    for (int c = 0; c < 4; c++)
                        rs[m][c >> 1] += ex2f(acc[m][n][c] * CEXP);
        } else {
            #pragma unroll
            for (int m = 0; m < 2; m++) {
                #pragma unroll
                for (int n = 0; n < 8; n++) {
                    #pragma unroll
                    for (int c = 0; c < 4; c++) {
                        float s = acc[m][n][c];
                        float e = ex2f(s * CEXP);
                        int gr = row_base + wm * 32 + m * 16 + ((c >> 1) << 3) + l4;
                        int gc = tile_col + wn * 64 + n * 8 + lm * 2 + (c & 1);
                        if (gc == gr) e = 0.0f;                    // mask diagonal
                        if (gc == ((gr + BHALF) & (NTOT - 1)))
                            g_pos[gr] = s * 2.0f;                  // sim = cos/T
                        rs[m][c >> 1] += e;
                    }
                }
            }
        }
    }

    // Reduce over the 4 lanes (lm) sharing each row, then one atomic per row
    #pragma unroll
    for (int m = 0; m < 2; m++)
        #pragma unroll
        for (int h = 0; h < 2; h++) {
            float v = rs[m][h];
            v += __shfl_xor_sync(0xffffffffu, v, 1);
            v += __shfl_xor_sync(0xffffffffu, v, 2);
            if (lm == 0)
                atomicAdd(&g_rowsum[row_base + wm * 32 + m * 16 + h * 8 + l4], v);
        }
}

// ---------------------------------------------------------------------------
__global__ void __launch_bounds__(1024) k_final(float* out) {
    __shared__ float red[32];
    const int tid = threadIdx.x;
    float acc = 0.0f;
    #pragma unroll
    for (int i = 0; i < 8; i++) {
        int r = tid + i * 1024;
        acc += __logf(g_rowsum[r]) - g_pos[r];        // lse - pos
    }
    #pragma unroll
    for (int o = 16; o; o >>= 1) acc += __shfl_xor_sync(0xffffffffu, acc, o);
    if ((tid & 31) == 0) red[tid >> 5] = acc;
    __syncthreads();
    if (tid < 32) {
        float v = red[tid];
        #pragma unroll
        for (int o = 16; o; o >>= 1) v += __shfl_xor_sync(0xffffffffu, v, o);
        if (tid == 0) out[0] = v * (1.0f / NTOT);
    }
}

// ---------------------------------------------------------------------------
extern "C" void kernel_launch(void* const* d_in, const int* in_sizes, int n_in,
                              void* d_out, int out_size) {
    const float* zi = (const float*)d_in[0];
    const float* zj = (const float*)d_in[1];
    float* out = (float*)d_out;

    const size_t smem = (size_t)TILE_B * 3;   // A + 2x B = 202,752 B
    cudaFuncSetAttribute(k_main, cudaFuncAttributeMaxDynamicSharedMemorySize, (int)smem);

    k_init<<<NTOT / 1024, 1024>>>();
    k_prep<<<NTOT / 8, 256>>>(zi, zj);
    k_main<<<(NTOT / MT) * 2, 256, smem>>>();
    k_final<<<1, 1024>>>(out);
}

// round 4
// speedup vs baseline: 2.4407x; 1.2534x over previous
#include <cuda_runtime.h>
#include <cuda_bf16.h>
#include <math.h>
#include <stdint.h>

#define NTOT   8192
#define BHALF  4096
#define DDIM   256
#define MT     128                  // rows per tile-block
#define CT     128                  // cols per tile
#define NRB    (NTOT / MT)          // 64 row-blocks
#define ASB    528                  // smem row stride bytes (264 bf16, conflict-free ldmatrix)
#define TILE_B (MT * ASB)           // 67584 bytes per tile buffer

// Scratch: normalized bf16 vectors, per-row sum-exp, per-row positive logit
__device__ __nv_bfloat16 g_zhat[NTOT * DDIM];
__device__ float g_rowsum[NTOT];
__device__ float g_pos[NTOT];
__device__ float g_accum;

// ---------------------------------------------------------------------------
__device__ __forceinline__ uint32_t smem_u32(const void* p) {
    uint32_t a;
    asm("{ .reg .u64 t; cvta.to.shared.u64 t, %1; cvt.u32.u64 %0, t; }"
        : "=r"(a) : "l"(p));
    return a;
}
__device__ __forceinline__ float ex2f(float x) {     // 2^x on MUFU pipe
    float r;
    asm("ex2.approx.f32 %0, %1;" : "=f"(r) : "f"(x));
    return r;
}
#define CP_ASYNC16(dst, src) \
    asm volatile("cp.async.cg.shared.global [%0], [%1], 16;" :: "r"(dst), "l"(src))
#define CP_COMMIT() asm volatile("cp.async.commit_group;" ::: "memory")
#define CP_WAIT(n)  asm volatile("cp.async.wait_group %0;" :: "n"(n) : "memory")

#define LDSM_X4(r0, r1, r2, r3, a)                                        \
    asm volatile("ldmatrix.sync.aligned.m8n8.x4.shared.b16 {%0,%1,%2,%3}, [%4];" \
        : "=r"(r0), "=r"(r1), "=r"(r2), "=r"(r3) : "r"(a))

#define MMA16816(d, a, b0, b1)                                            \
    asm volatile("mma.sync.aligned.m16n8k16.row.col.f32.bf16.bf16.f32 "   \
        "{%0,%1,%2,%3}, {%4,%5,%6,%7}, {%8,%9}, {%0,%1,%2,%3};"           \
        : "+f"((d)[0]), "+f"((d)[1]), "+f"((d)[2]), "+f"((d)[3])          \
        : "r"((a)[0]), "r"((a)[1]), "r"((a)[2]), "r"((a)[3]), "r"(b0), "r"(b1))

// ---------------------------------------------------------------------------
__global__ void k_init() {
    g_rowsum[blockIdx.x * 1024 + threadIdx.x] = 0.0f;
    if (blockIdx.x == 0 && threadIdx.x == 0) g_accum = 0.0f;
}

// One warp per row: norm + normalize + bf16 store
__global__ void k_prep(const float* __restrict__ zi, const float* __restrict__ zj) {
    int row  = blockIdx.x * 8 + (threadIdx.x >> 5);
    int lane = threadIdx.x & 31;
    const float* src = (row < BHALF) ? (zi + (size_t)row * DDIM)
                                     : (zj + (size_t)(row - BHALF) * DDIM);
    float4 v0 = ((const float4*)src)[lane * 2 + 0];
    float4 v1 = ((const float4*)src)[lane * 2 + 1];
    float ss = v0.x*v0.x + v0.y*v0.y + v0.z*v0.z + v0.w*v0.w
             + v1.x*v1.x + v1.y*v1.y + v1.z*v1.z + v1.w*v1.w;
    #pragma unroll
    for (int o = 16; o; o >>= 1) ss += __shfl_xor_sync(0xffffffffu, ss, o);
    float rinv = rsqrtf(ss);   // norms ~16 for N(0,1) D=256: eps never binds

    __nv_bfloat162 h0 = __floats2bfloat162_rn(v0.x * rinv, v0.y * rinv);
    __nv_bfloat162 h1 = __floats2bfloat162_rn(v0.z * rinv, v0.w * rinv);
    __nv_bfloat162 h2 = __floats2bfloat162_rn(v1.x * rinv, v1.y * rinv);
    __nv_bfloat162 h3 = __floats2bfloat162_rn(v1.z * rinv, v1.w * rinv);
    uint4 pack;
    pack.x = *(uint32_t*)&h0;  pack.y = *(uint32_t*)&h1;
    pack.z = *(uint32_t*)&h2;  pack.w = *(uint32_t*)&h3;
    *(uint4*)(g_zhat + (size_t)row * DDIM + lane * 8) = pack;
}

// ---------------------------------------------------------------------------
__device__ __forceinline__ void load_tile_async(uint32_t dst, int grow0) {
    const int tid = threadIdx.x;
    #pragma unroll
    for (int i = 0; i < 16; i++) {
        int c   = tid + i * 256;
        int r   = c >> 5;
        int off = (c & 31) * 16;
        CP_ASYNC16(dst + r * ASB + off,
                   (const char*)g_zhat + (size_t)(grow0 + r) * 512 + off);
    }
}

// ---------------------------------------------------------------------------
// Upper-triangle tile sweep with symmetry: tile (I,J), I<=J, computed once.
// Off-diagonal tiles contribute exp() to BOTH row-block I sums (registers)
// and row-block J sums (shuffle + shared-atomic column reduction).
// Strip pairing: pair p handles row-blocks {p, 63-p} -> 65 tiles, split over
// 4 column-chunks -> grid 128 CTAs, one wave.
// ---------------------------------------------------------------------------
__global__ void __launch_bounds__(256) k_main() {
    extern __shared__ char sm[];
    __shared__ float scol[CT];
    const uint32_t sA  = smem_u32(sm);
    const uint32_t sB0 = sA + TILE_B;

    const int tid  = threadIdx.x;
    const int lane = tid & 31;
    const int warp = tid >> 5;
    const int wm   = warp & 3;             // M subtile (32 rows)
    const int wn   = warp >> 2;            // N half (64 cols)
    const int l4   = lane >> 2;
    const int lm   = lane & 3;

    const int p    = blockIdx.x >> 2;      // strip pair 0..31
    const int h    = blockIdx.x & 3;       // column chunk 0..3
    const int len1 = NRB - p;              // tiles in row-block p (J=p..63)
    const int t0   = (65 * h) >> 2;
    const int t1   = (65 * (h + 1)) >> 2;

    // ldmatrix per-lane base offsets (bytes); k-step adds ks*32
    uint32_t aoff[2];
    #pragma unroll
    for (int m = 0; m < 2; m++) {
        int arow = wm * 32 + m * 16 + (lane & 15);
        aoff[m] = sA + (uint32_t)arow * ASB + (uint32_t)(lane >> 4) * 16;
    }
    uint32_t boff[4];
    #pragma unroll
    for (int nt = 0; nt < 4; nt++) {
        int brow = wn * 64 + nt * 16 + (lane & 7) + ((lane >> 4) << 3);
        boff[nt] = (uint32_t)brow * ASB + (uint32_t)((lane >> 3) & 1) * 16;
    }

    if (tid < CT) scol[tid] = 0.0f;

    #define I_OF(t) (((t) < len1) ? p : (NRB - 1 - p))
    #define J_OF(t) (((t) < len1) ? (p + (t)) : ((NRB - 1 - p) + ((t) - len1)))

    int curI = I_OF(t0);
    load_tile_async(sA, curI * MT);
    load_tile_async(sB0, J_OF(t0) * CT);
    CP_COMMIT();

    const float CEXP = 2.8853900817779268f;      // log2(e)/T, T = 0.5
    float rs[2][2] = {{0.f, 0.f}, {0.f, 0.f}};

    for (int t = t0; t < t1; t++) {
        const int J = J_OF(t);
        const uint32_t bufc = sB0 + (uint32_t)((t - t0) & 1) * TILE_B;
        __syncthreads();   // prev tile reads done; scol zeroing visible
        const bool nextSame = (t + 1 < t1) && (I_OF(t + 1) == curI);
        if (nextSame) {
            load_tile_async(sB0 + (uint32_t)((t + 1 - t0) & 1) * TILE_B,
                            J_OF(t + 1) * CT);
            CP_COMMIT();
            CP_WAIT(1);
        } else {
            CP_WAIT(0);
        }
        __syncthreads();

        float acc[2][8][4];
        #pragma unroll
        for (int m = 0; m < 2; m++)
            #pragma unroll
            for (int n = 0; n < 8; n++)
                #pragma unroll
                for (int c = 0; c < 4; c++) acc[m][n][c] = 0.0f;

        #pragma unroll
        for (int ks = 0; ks < 16; ks++) {
            const uint32_t kb = (uint32_t)ks * 32;
            uint32_t a[2][4], b[4][4];
            #pragma unroll
            for (int m = 0; m < 2; m++)
                LDSM_X4(a[m][0], a[m][1], a[m][2], a[m][3], aoff[m] + kb);
            #pragma unroll
            for (int nt = 0; nt < 4; nt++)
                LDSM_X4(b[nt][0], b[nt][1], b[nt][2], b[nt][3], bufc + boff[nt] + kb);
            #pragma unroll
            for (int m = 0; m < 2; m++)
                #pragma unroll
                for (int nt = 0; nt < 4; nt++) {
                    MMA16816(acc[m][nt * 2 + 0], a[m], b[nt][0], b[nt][1]);
                    MMA16816(acc[m][nt * 2 + 1], a[m], b[nt][2], b[nt][3]);
                }
        }

        // ---- epilogue ----
        const bool isDiag = (curI == J);
        const bool isPos  = (J == curI + BHALF / CT);
        const int rowb = curI * MT, colb = J * CT;
        float cs[16];
        #pragma unroll
        for (int k = 0; k < 16; k++) cs[k] = 0.0f;

        #pragma unroll
        for (int m = 0; m < 2; m++) {
            #pragma unroll
            for (int n = 0; n < 8; n++) {
                #pragma unroll
                for (int c = 0; c < 4; c++) {
                    float s = acc[m][n][c];
                    float e = ex2f(s * CEXP);
                    if (isDiag) {
                        int gr = rowb + wm * 32 + m * 16 + ((c >> 1) << 3) + l4;
                        int gc = colb + wn * 64 + n * 8 + lm * 2 + (c & 1);
                        if (gc == gr) e = 0.0f;      // mask self-similarity
                    } else {
                        if (isPos) {
                            int gr = rowb + wm * 32 + m * 16 + ((c >> 1) << 3) + l4;
                            int gc = colb + wn * 64 + n * 8 + lm * 2 + (c & 1);
                            if (gc == gr + BHALF) {  // positive pair (once per row)
                                g_pos[gr] = s * 2.0f;        // sim = cos/T
                                g_pos[gc] = s * 2.0f;        // symmetric partner
                            }
                        }
                        cs[n * 2 + (c & 1)] += e;    // column partial (symmetry)
                    }
                    rs[m][c >> 1] += e;              // row partial
                }
            }
        }

        if (!isDiag) {
            // reduce col partials over l4 (lanes stride 4), then to shared
            #pragma unroll
            for (int k = 0; k < 16; k++) {
                float v = cs[k];
                v += __shfl_xor_sync(0xffffffffu, v, 4);
                v += __shfl_xor_sync(0xffffffffu, v, 8);
                v += __shfl_xor_sync(0xffffffffu, v, 16);
                cs[k] = v;
            }
            if (l4 == 0) {
                #pragma unroll
                for (int k = 0; k < 16; k++)
                    atomicAdd(&scol[wn * 64 + (k >> 1) * 8 + lm * 2 + (k & 1)], cs[k]);
            }
            __syncthreads();
            if (tid < CT) {
                atomicAdd(&g_rowsum[colb + tid], scol[tid]);
                scol[tid] = 0.0f;     // next-tile reuse; ordered by loop-top sync
            }
        }

        // phase switch: flush row sums for curI, reload A in place
        if (t + 1 < t1 && !nextSame) {
            #pragma unroll
            for (int m = 0; m < 2; m++)
                #pragma unroll
                for (int h2 = 0; h2 < 2; h2++) {
                    float v = rs[m][h2];
                    v += __shfl_xor_sync(0xffffffffu, v, 1);
                    v += __shfl_xor_sync(0xffffffffu, v, 2);
                    if (lm == 0)
                        atomicAdd(&g_rowsum[curI * MT + wm * 32 + m * 16 + h2 * 8 + l4], v);
                    rs[m][h2] = 0.0f;
                }
            __syncthreads();          // all warps done with old A
            curI = I_OF(t + 1);
            load_tile_async(sA, curI * MT);
            load_tile_async(sB0 + (uint32_t)((t + 1 - t0) & 1) * TILE_B,
                            J_OF(t + 1) * CT);
            CP_COMMIT();
        }
    }

    // final row-sum flush
    #pragma unroll
    for (int m = 0; m < 2; m++)
        #pragma unroll
        for (int h2 = 0; h2 < 2; h2++) {
            float v = rs[m][h2];
            v += __shfl_xor_sync(0xffffffffu, v, 1);
            v += __shfl_xor_sync(0xffffffffu, v, 2);
            if (lm == 0)
                atomicAdd(&g_rowsum[curI * MT + wm * 32 + m * 16 + h2 * 8 + l4], v);
        }
    #undef I_OF
    #undef J_OF
}

// ---------------------------------------------------------------------------
__global__ void __launch_bounds__(1024) k_final() {
    __shared__ float red[32];
    const int tid = threadIdx.x;
    const int r = blockIdx.x * 1024 + tid;
    float acc = __logf(g_rowsum[r]) - g_pos[r];      // lse - pos
    #pragma unroll
    for (int o = 16; o; o >>= 1) acc += __shfl_xor_sync(0xffffffffu, acc, o);
    if ((tid & 31) == 0) red[tid >> 5] = acc;
    __syncthreads();
    if (tid < 32) {
        float v = red[tid];
        #pragma unroll
        for (int o = 16; o; o >>= 1) v += __shfl_xor_sync(0xffffffffu, v, o);
        if (tid == 0) atomicAdd(&g_accum, v);
    }
}

__global__ void k_write(float* out) { out[0] = g_accum * (1.0f / NTOT); }

// ---------------------------------------------------------------------------
extern "C" void kernel_launch(void* const* d_in, const int* in_sizes, int n_in,
                              void* d_out, int out_size) {
    const float* zi = (const float*)d_in[0];
    const float* zj = (const float*)d_in[1];
    float* out = (float*)d_out;

    const size_t smem = (size_t)TILE_B * 3;   // A + 2x B = 202,752 B
    cudaFuncSetAttribute(k_main, cudaFuncAttributeMaxDynamicSharedMemorySize, (int)smem);

    k_init<<<NTOT / 1024, 1024>>>();
    k_prep<<<NTOT / 8, 256>>>(zi, zj);
    k_main<<<128, 256, smem>>>();
    k_final<<<NTOT / 1024, 1024>>>();
    k_write<<<1, 1>>>(out);
}

// round 5
// speedup vs baseline: 4.6685x; 1.9128x over previous
#include <cuda_runtime.h>
#include <cuda_bf16.h>
#include <math.h>
#include <stdint.h>

#define NTOT   8192
#define BHALF  4096
#define DDIM   256
#define MT     128                  // rows per tile-block
#define CT     128                  // cols per tile
#define NRB    (NTOT / MT)          // 64 row-blocks
#define AS8    272                  // smem row stride bytes (256 data + 16 pad)
#define TILE8  (MT * AS8)           // 34816 bytes per tile buffer
#define NCHUNK 9                    // chunks per strip-pair -> grid 288, 2 CTAs/SM

// Scratch: int8-quantized normalized vectors (q = round(127*zhat)),
// per-row sum-exp, per-row positive logit
__device__ int8_t g_q[NTOT * DDIM];
__device__ float g_rowsum[NTOT];
__device__ float g_pos[NTOT];

// ---------------------------------------------------------------------------
__device__ __forceinline__ uint32_t smem_u32(const void* p) {
    uint32_t a;
    asm("{ .reg .u64 t; cvta.to.shared.u64 t, %1; cvt.u32.u64 %0, t; }"
        : "=r"(a) : "l"(p));
    return a;
}
__device__ __forceinline__ float ex2f(float x) {     // 2^x on MUFU pipe
    float r;
    asm("ex2.approx.f32 %0, %1;" : "=f"(r) : "f"(x));
    return r;
}
#define CP_ASYNC16(dst, src) \
    asm volatile("cp.async.cg.shared.global [%0], [%1], 16;" :: "r"(dst), "l"(src))
#define CP_COMMIT() asm volatile("cp.async.commit_group;" ::: "memory")
#define CP_WAIT(n)  asm volatile("cp.async.wait_group %0;" :: "n"(n) : "memory")

#define LDSM_X4(r0, r1, r2, r3, a)                                        \
    asm volatile("ldmatrix.sync.aligned.m8n8.x4.shared.b16 {%0,%1,%2,%3}, [%4];" \
        : "=r"(r0), "=r"(r1), "=r"(r2), "=r"(r3) : "r"(a))

#define MMAS8(d, a0, a1, a2, a3, b0, b1)                                  \
    asm volatile("mma.sync.aligned.m16n8k32.row.col.s32.s8.s8.s32 "       \
        "{%0,%1,%2,%3}, {%4,%5,%6,%7}, {%8,%9}, {%0,%1,%2,%3};"           \
        : "+r"((d)[0]), "+r"((d)[1]), "+r"((d)[2]), "+r"((d)[3])          \
        : "r"(a0), "r"(a1), "r"(a2), "r"(a3), "r"(b0), "r"(b1))

// ---------------------------------------------------------------------------
// Prep: one warp per row — norm, normalize, quantize to int8, pack.
// Also zeroes g_rowsum (first 32 blocks).
// ---------------------------------------------------------------------------
__global__ void k_prep(const float* __restrict__ zi, const float* __restrict__ zj) {
    if (blockIdx.x < 32) g_rowsum[blockIdx.x * 256 + threadIdx.x] = 0.0f;

    int row  = blockIdx.x * 8 + (threadIdx.x >> 5);
    int lane = threadIdx.x & 31;
    const float* src = (row < BHALF) ? (zi + (size_t)row * DDIM)
                                     : (zj + (size_t)(row - BHALF) * DDIM);
    float4 v0 = ((const float4*)src)[lane * 2 + 0];
    float4 v1 = ((const float4*)src)[lane * 2 + 1];
    float ss = v0.x*v0.x + v0.y*v0.y + v0.z*v0.z + v0.w*v0.w
             + v1.x*v1.x + v1.y*v1.y + v1.z*v1.z + v1.w*v1.w;
    #pragma unroll
    for (int o = 16; o; o >>= 1) ss += __shfl_xor_sync(0xffffffffu, ss, o);
    float sc = 127.0f * rsqrtf(ss);    // norms ~16 for N(0,1) D=256: eps never binds

    int q[8];
    q[0] = __float2int_rn(v0.x * sc);  q[1] = __float2int_rn(v0.y * sc);
    q[2] = __float2int_rn(v0.z * sc);  q[3] = __float2int_rn(v0.w * sc);
    q[4] = __float2int_rn(v1.x * sc);  q[5] = __float2int_rn(v1.y * sc);
    q[6] = __float2int_rn(v1.z * sc);  q[7] = __float2int_rn(v1.w * sc);
    uint2 pk;
    pk.x = (q[0] & 0xff) | ((q[1] & 0xff) << 8) | ((q[2] & 0xff) << 16) | (q[3] << 24);
    pk.y = (q[4] & 0xff) | ((q[5] & 0xff) << 8) | ((q[6] & 0xff) << 16) | (q[7] << 24);
    *(uint2*)(g_q + (size_t)row * DDIM + lane * 8) = pk;
}

// ---------------------------------------------------------------------------
// Async tile loader: 128 rows x 256 int8 (256B payload per 272B smem row).
// 2048 16B chunks over 256 threads x 8 iters.
// ---------------------------------------------------------------------------
__device__ __forceinline__ void load_tile_async(uint32_t dst, int grow0) {
    const int tid = threadIdx.x;
    #pragma unroll
    for (int i = 0; i < 8; i++) {
        int c   = tid + i * 256;
        int r   = c >> 4;
        int off = (c & 15) * 16;
        CP_ASYNC16(dst + r * AS8 + off,
                   (const char*)g_q + (size_t)(grow0 + r) * 256 + off);
    }
}

// ---------------------------------------------------------------------------
// Upper-triangle tile sweep with symmetry (see R4). int8 mma m16n8k32.
// Grid 288 = 32 strip-pairs x 9 chunks; 2 CTAs/SM.
// ---------------------------------------------------------------------------
__global__ void __launch_bounds__(256) k_main() {
    extern __shared__ char sm[];
    __shared__ float scol[CT];
    const uint32_t sA  = smem_u32(sm);
    const uint32_t sB0 = sA + TILE8;

    const int tid  = threadIdx.x;
    const int lane = tid & 31;
    const int warp = tid >> 5;
    const int wm   = warp & 3;             // M subtile (32 rows)
    const int wn   = warp >> 2;            // N half (64 cols)
    const int l4   = lane >> 2;
    const int lm   = lane & 3;

    const int p    = blockIdx.x / NCHUNK;  // strip pair 0..31
    const int h    = blockIdx.x % NCHUNK;  // chunk 0..8
    const int len1 = NRB - p;              // tiles in row-block p (J = p..63)
    const int t0   = (65 * h) / NCHUNK;
    const int t1   = (65 * (h + 1)) / NCHUNK;

    // ldmatrix per-lane base offsets (bytes); k-step adds ks*32
    uint32_t aoff[2];
    #pragma unroll
    for (int m = 0; m < 2; m++) {
        int arow = wm * 32 + m * 16 + (lane & 15);
        aoff[m] = sA + (uint32_t)arow * AS8 + (uint32_t)(lane >> 4) * 16;
    }
    uint32_t boff[4];
    #pragma unroll
    for (int nt = 0; nt < 4; nt++) {
        int brow = wn * 64 + nt * 16 + (lane & 7) + ((lane >> 4) << 3);
        boff[nt] = (uint32_t)brow * AS8 + (uint32_t)((lane >> 3) & 1) * 16;
    }

    if (tid < CT) scol[tid] = 0.0f;

    #define I_OF(t) (((t) < len1) ? p : (NRB - 1 - p))
    #define J_OF(t) (((t) < len1) ? (p + (t)) : ((NRB - 1 - p) + ((t) - len1)))

    int curI = I_OF(t0);
    load_tile_async(sA, curI * MT);
    load_tile_async(sB0, J_OF(t0) * CT);
    CP_COMMIT();

    // exp(cos/T) = 2^(dot_i32 * KQ);  KQ = log2(e)/(T*127^2)
    const float KQ   = 2.8853900817779268f / 16129.0f;
    const float MAGF = 12582912.0f;               // 1.5 * 2^23
    const int   MAGI = 0x4B400000;
    float rs[2][2] = {{0.f, 0.f}, {0.f, 0.f}};

    for (int t = t0; t < t1; t++) {
        const int J = J_OF(t);
        const uint32_t bufc = sB0 + (uint32_t)((t - t0) & 1) * TILE8;
        __syncthreads();   // prev tile reads done; scol state settled
        const bool nextSame = (t + 1 < t1) && (I_OF(t + 1) == curI);
        if (nextSame) {
            load_tile_async(sB0 + (uint32_t)((t + 1 - t0) & 1) * TILE8,
                            J_OF(t + 1) * CT);
            CP_COMMIT();
            CP_WAIT(1);
        } else {
            CP_WAIT(0);
        }
        __syncthreads();

        int acc[2][8][4];
        #pragma unroll
        for (int m = 0; m < 2; m++)
            #pragma unroll
            for (int n = 0; n < 8; n++)
                #pragma unroll
                for (int c = 0; c < 4; c++) acc[m][n][c] = 0;

        #pragma unroll
        for (int ks = 0; ks < 8; ks++) {
            const uint32_t kb = (uint32_t)ks * 32;
            uint32_t a[2][4], b[4][4];
            #pragma unroll
            for (int m = 0; m < 2; m++)
                LDSM_X4(a[m][0], a[m][1], a[m][2], a[m][3], aoff[m] + kb);
            #pragma unroll
            for (int nt = 0; nt < 4; nt++)
                LDSM_X4(b[nt][0], b[nt][1], b[nt][2], b[nt][3], bufc + boff[nt] + kb);
            #pragma unroll
            for (int m = 0; m < 2; m++)
                #pragma unroll
                for (int nt = 0; nt < 4; nt++) {
                    MMAS8(acc[m][nt * 2 + 0], a[m][0], a[m][1], a[m][2], a[m][3],
                          b[nt][0], b[nt][1]);
                    MMAS8(acc[m][nt * 2 + 1], a[m][0], a[m][1], a[m][2], a[m][3],
                          b[nt][2], b[nt][3]);
                }
        }

        // ---- epilogue ----
        const bool isDiag = (curI == J);
        const bool isPos  = (J == curI + BHALF / CT);
        const int rowb = curI * MT, colb = J * CT;
        float cs[16];
        #pragma unroll
        for (int k = 0; k < 16; k++) cs[k] = 0.0f;

        #pragma unroll
        for (int m = 0; m < 2; m++) {
            #pragma unroll
            for (int n = 0; n < 8; n++) {
                #pragma unroll
                for (int c = 0; c < 4; c++) {
                    // exact i32->f32 via magic (|dot| <= 4.13e6 < 2^22)
                    float f = __int_as_float(MAGI + acc[m][n][c]) - MAGF;
                    float e = ex2f(f * KQ);
                    if (isDiag) {
                        int gr = rowb + wm * 32 + m * 16 + ((c >> 1) << 3) + l4;
                        int gc = colb + wn * 64 + n * 8 + lm * 2 + (c & 1);
                        if (gc == gr) e = 0.0f;      // mask self-similarity
                    } else {
                        if (isPos) {
                            int gr = rowb + wm * 32 + m * 16 + ((c >> 1) << 3) + l4;
                            int gc = colb + wn * 64 + n * 8 + lm * 2 + (c & 1);
                            if (gc == gr + BHALF) {  // positive pair
                                float pv = f * (2.0f / 16129.0f);   // sim = cos/T
                                g_pos[gr] = pv;
                                g_pos[gc] = pv;      // symmetric partner
                            }
                        }
                        cs[n * 2 + (c & 1)] += e;    // column partial (symmetry)
                    }
                    rs[m][c >> 1] += e;              // row partial
                }
            }
        }

        if (!isDiag) {
            #pragma unroll
            for (int k = 0; k < 16; k++) {
                float v = cs[k];
                v += __shfl_xor_sync(0xffffffffu, v, 4);
                v += __shfl_xor_sync(0xffffffffu, v, 8);
                v += __shfl_xor_sync(0xffffffffu, v, 16);
                cs[k] = v;
            }
            if (l4 == 0) {
                #pragma unroll
                for (int k = 0; k < 16; k++)
                    atomicAdd(&scol[wn * 64 + (k >> 1) * 8 + lm * 2 + (k & 1)], cs[k]);
            }
            __syncthreads();
            if (tid < CT) {
                atomicAdd(&g_rowsum[colb + tid], scol[tid]);
                scol[tid] = 0.0f;     // reused next tile; ordered by loop-top sync
            }
        }

        // phase switch: flush row sums for curI, reload A in place
        if (t + 1 < t1 && !nextSame) {
            #pragma unroll
            for (int m = 0; m < 2; m++)
                #pragma unroll
                for (int h2 = 0; h2 < 2; h2++) {
                    float v = rs[m][h2];
                    v += __shfl_xor_sync(0xffffffffu, v, 1);
                    v += __shfl_xor_sync(0xffffffffu, v, 2);
                    if (lm == 0)
                        atomicAdd(&g_rowsum[curI * MT + wm * 32 + m * 16 + h2 * 8 + l4], v);
                    rs[m][h2] = 0.0f;
                }
            __syncthreads();          // all warps done with old A
            curI = I_OF(t + 1);
            load_tile_async(sA, curI * MT);
            load_tile_async(sB0 + (uint32_t)((t + 1 - t0) & 1) * TILE8,
                            J_OF(t + 1) * CT);
            CP_COMMIT();
        }
    }

    // final row-sum flush
    #pragma unroll
    for (int m = 0; m < 2; m++)
        #pragma unroll
        for (int h2 = 0; h2 < 2; h2++) {
            float v = rs[m][h2];
            v += __shfl_xor_sync(0xffffffffu, v, 1);
            v += __shfl_xor_sync(0xffffffffu, v, 2);
            if (lm == 0)
                atomicAdd(&g_rowsum[curI * MT + wm * 32 + m * 16 + h2 * 8 + l4], v);
        }
    #undef I_OF
    #undef J_OF
}

// ---------------------------------------------------------------------------
// Final: single block, vectorized; writes the scalar loss directly.
// ---------------------------------------------------------------------------
__global__ void __launch_bounds__(1024) k_final(float* out) {
    __shared__ float red[32];
    const int tid = threadIdx.x;
    const int r0 = tid * 8;
    float4 s0 = *(const float4*)(g_rowsum + r0);
    float4 s1 = *(const float4*)(g_rowsum + r0 + 4);
    float4 p0 = *(const float4*)(g_pos + r0);
    float4 p1 = *(const float4*)(g_pos + r0 + 4);
    float acc = (__logf(s0.x) - p0.x) + (__logf(s0.y) - p0.y)
              + (__logf(s0.z) - p0.z) + (__logf(s0.w) - p0.w)
              + (__logf(s1.x) - p1.x) + (__logf(s1.y) - p1.y)
              + (__logf(s1.z) - p1.z) + (__logf(s1.w) - p1.w);
    #pragma unroll
    for (int o = 16; o; o >>= 1) acc += __shfl_xor_sync(0xffffffffu, acc, o);
    if ((tid & 31) == 0) red[tid >> 5] = acc;
    __syncthreads();
    if (tid < 32) {
        float v = red[tid];
        #pragma unroll
        for (int o = 16; o; o >>= 1) v += __shfl_xor_sync(0xffffffffu, v, o);
        if (tid == 0) out[0] = v * (1.0f / NTOT);
    }
}

// ---------------------------------------------------------------------------
extern "C" void kernel_launch(void* const* d_in, const int* in_sizes, int n_in,
                              void* d_out, int out_size) {
    const float* zi = (const float*)d_in[0];
    const float* zj = (const float*)d_in[1];
    float* out = (float*)d_out;

    const size_t smem = (size_t)TILE8 * 3;   // A + 2x B = 104,448 B (2 CTAs/SM)
    cudaFuncSetAttribute(k_main, cudaFuncAttributeMaxDynamicSharedMemorySize, (int)smem);

    k_prep<<<NTOT / 8, 256>>>(zi, zj);
    k_main<<<32 * NCHUNK, 256, smem>>>();
    k_final<<<1, 1024>>>(out);
}